// round 15
// baseline (speedup 1.0000x reference)
#include <cuda_runtime.h>
#include <cuda_fp16.h>
#include <cuda_bf16.h>
#include <cstdint>

// Problem constants (fixed shapes from reference)
#define BATCH      16
#define TLEN       1024
#define CCH        32
#define TC         (TLEN * CCH)        // 32768
#define KDIM       128
#define S_MAIN     128
#define NB_PATCH   400
#define P_TOP      60
#define P_OUT      (NB_PATCH + P_TOP)  // 460
#define STRETCH    8

#define THREADS    512                 // 16 warps; each warp owns 2 tasks/phase
#define TPB        32                  // tasks (p columns) per phase
#define NPH        2                   // phases (st rows) per block
#define SB         17                  // s_res row stride (conflict-free)
#define MAIN_PB    ((NB_PATCH + TPB - 1) / TPB)  // 13 (last width 16)
#define MAIN_BLK2  ((S_MAIN / NPH) * MAIN_PB)    // 64*13 = 832
#define TOP_BLK2   ((TLEN / NPH) * 2)            // 512*2 = 1024
#define ALL_BLK2   (MAIN_BLK2 + TOP_BLK2)        // 1856
#define MAIN_STEP  (S_MAIN / NPH)      // 64
#define TOP_STEP   (TLEN / NPH)        // 512

// Scratch: transposed fp16 x, xTh[tc][b]. One gather index pulls 16 halves
// = 32B (one L2 sector) holding all 16 batch values.
__device__ __align__(32) __half g_xTh[TC * BATCH];

// --------------------------------------------------------------------------
// Kernel 1: transpose + fp16-quantize x [B, T*C] -> xTh [T*C, B]
// --------------------------------------------------------------------------
__global__ void transpose_x_kernel(const float* __restrict__ x) {
    int tc = blockIdx.x * blockDim.x + threadIdx.x;
    if (tc >= TC) return;
    __half2 h[8];
#pragma unroll
    for (int b = 0; b < 8; b++) {
        h[b] = __floats2half2_rn(x[(2 * b) * TC + tc], x[(2 * b + 1) * TC + tc]);
    }
    uint4* dst = reinterpret_cast<uint4*>(g_xTh + tc * BATCH);
    unsigned int* hu = reinterpret_cast<unsigned int*>(h);
    dst[0] = make_uint4(hu[0], hu[1], hu[2], hu[3]);
    dst[1] = make_uint4(hu[4], hu[5], hu[6], hu[7]);
}

// --------------------------------------------------------------------------
// Kernel 2: fused main + top patch layers.
// Block = 16 warps covering 32 consecutive p of TWO (s|t) rows (phases),
// same p-range both phases so widths match. Phase loop is #pragma unroll 1:
// the R13 hot loop stays ONE static code copy executed twice (like an outer
// m-iteration) — no schedule perturbation, half the blocks/barriers/tails.
// Warp w owns tasks pA = w and pB = w+16 per phase: two INDEPENDENT
// gather->FMA chains. Absent B task aliases pA (warp-uniform pointer SEL;
// duplicate gathers become L1 hits).
// Lane = (q = lane>>2, c = lane&3):
//   - idx/W per chain: int4/float4 at [m*8+q] (128B per warp-load, 1 wf),
//   - gathers: quad q fetches row idx, lane reads 8B (batches 4c..4c+3),
//   - reduce via shfl_xor(4,8,16); q==0 lanes hold all 16 batches,
//   - padded smem stage (64 rows); ONE barrier; store: warp = batch,
//     32 lanes = 32 consecutive p (128B rows), both phases.
// --------------------------------------------------------------------------
__global__ __launch_bounds__(THREADS, 2) void patchy_kernel(
    const float* __restrict__ W_main, const float* __restrict__ b_main,
    const float* __restrict__ W_top,  const float* __restrict__ b_top,
    const int*   __restrict__ idx_main, const int* __restrict__ idx_top,
    float* __restrict__ out)
{
    __shared__ float s_res[NPH * TPB * SB];

    const int tid  = threadIdx.x;
    const int w    = tid >> 5;       // warp id: local pA (compute) / batch (store)
    const int lane = tid & 31;
    const int q    = lane >> 2;      // quad: sub-index group
    const int c    = lane & 3;       // component: batches 4c..4c+3
    const bool is_main = (blockIdx.x < MAIN_BLK2);

    int row, p0, width, st_step;
    if (is_main) {
        row     = blockIdx.x / MAIN_PB;                 // 0..63
        p0      = (blockIdx.x - row * MAIN_PB) * TPB;
        width   = min(TPB, NB_PATCH - p0);
        st_step = MAIN_STEP;
    } else {
        const int b2 = blockIdx.x - MAIN_BLK2;          // 0..1023
        row     = b2 >> 1;                              // 0..511
        p0      = (b2 & 1) * TPB;
        width   = min(TPB, P_TOP - p0);
        st_step = TOP_STEP;
    }

    // Two tasks per warp; absent task aliases pA (gathers become L1 hits).
    const int  pA   = w;
    const int  pB   = w + 16;
    const bool hasB = (pB < width);
    const int  pBc  = hasB ? pB : pA;

    const uint2* __restrict__ xT2 = reinterpret_cast<const uint2*>(g_xTh);

#pragma unroll 1
    for (int ph = 0; ph < NPH; ph++) {
        const int st = row + ph * st_step;
        const int*   gi;
        const float* gw;
        const float* gb;
        if (is_main) {
            const long base = ((long)st * NB_PATCH + p0) * KDIM;
            gi = idx_main + base;
            gw = W_main   + base;
            gb = b_main   + st * NB_PATCH + p0;
        } else {
            const long base = ((long)st * P_TOP + p0) * KDIM;
            gi = idx_top + base;
            gw = W_top   + base;
            gb = b_top   + st * P_TOP + p0;
        }

        const int4*   ipA = reinterpret_cast<const int4*>(gi + pA  * KDIM);
        const int4*   ipB = reinterpret_cast<const int4*>(gi + pBc * KDIM);
        const float4* wpA = reinterpret_cast<const float4*>(gw + pA  * KDIM);
        const float4* wpB = reinterpret_cast<const float4*>(gw + pBc * KDIM);

        float4 accA = make_float4(0.f, 0.f, 0.f, 0.f);
        float4 accB = make_float4(0.f, 0.f, 0.f, 0.f);

#pragma unroll
        for (int m = 0; m < 4; m++) {
            // Interleaved independent chains: A's and B's gathers are both
            // in flight while either chain's FMAs execute.
            const int4 IA = ipA[m * 8 + q];
            const int4 IB = ipB[m * 8 + q];

            const uint2 gA0 = xT2[IA.x * 4 + c];
            const uint2 gA1 = xT2[IA.y * 4 + c];
            const uint2 gA2 = xT2[IA.z * 4 + c];
            const uint2 gA3 = xT2[IA.w * 4 + c];
            const uint2 gB0 = xT2[IB.x * 4 + c];
            const uint2 gB1 = xT2[IB.y * 4 + c];
            const uint2 gB2 = xT2[IB.z * 4 + c];
            const uint2 gB3 = xT2[IB.w * 4 + c];

            const float4 WA = wpA[m * 8 + q];
            const float4 WB = wpB[m * 8 + q];

            {
                const float2 l0 = __half22float2(*reinterpret_cast<const __half2*>(&gA0.x));
                const float2 h0 = __half22float2(*reinterpret_cast<const __half2*>(&gA0.y));
                accA.x = fmaf(l0.x, WA.x, accA.x); accA.y = fmaf(l0.y, WA.x, accA.y);
                accA.z = fmaf(h0.x, WA.x, accA.z); accA.w = fmaf(h0.y, WA.x, accA.w);
                const float2 l1 = __half22float2(*reinterpret_cast<const __half2*>(&gA1.x));
                const float2 h1 = __half22float2(*reinterpret_cast<const __half2*>(&gA1.y));
                accA.x = fmaf(l1.x, WA.y, accA.x); accA.y = fmaf(l1.y, WA.y, accA.y);
                accA.z = fmaf(h1.x, WA.y, accA.z); accA.w = fmaf(h1.y, WA.y, accA.w);
                const float2 l2 = __half22float2(*reinterpret_cast<const __half2*>(&gA2.x));
                const float2 h2 = __half22float2(*reinterpret_cast<const __half2*>(&gA2.y));
                accA.x = fmaf(l2.x, WA.z, accA.x); accA.y = fmaf(l2.y, WA.z, accA.y);
                accA.z = fmaf(h2.x, WA.z, accA.z); accA.w = fmaf(h2.y, WA.z, accA.w);
                const float2 l3 = __half22float2(*reinterpret_cast<const __half2*>(&gA3.x));
                const float2 h3 = __half22float2(*reinterpret_cast<const __half2*>(&gA3.y));
                accA.x = fmaf(l3.x, WA.w, accA.x); accA.y = fmaf(l3.y, WA.w, accA.y);
                accA.z = fmaf(h3.x, WA.w, accA.z); accA.w = fmaf(h3.y, WA.w, accA.w);
            }
            {
                const float2 l0 = __half22float2(*reinterpret_cast<const __half2*>(&gB0.x));
                const float2 h0 = __half22float2(*reinterpret_cast<const __half2*>(&gB0.y));
                accB.x = fmaf(l0.x, WB.x, accB.x); accB.y = fmaf(l0.y, WB.x, accB.y);
                accB.z = fmaf(h0.x, WB.x, accB.z); accB.w = fmaf(h0.y, WB.x, accB.w);
                const float2 l1 = __half22float2(*reinterpret_cast<const __half2*>(&gB1.x));
                const float2 h1 = __half22float2(*reinterpret_cast<const __half2*>(&gB1.y));
                accB.x = fmaf(l1.x, WB.y, accB.x); accB.y = fmaf(l1.y, WB.y, accB.y);
                accB.z = fmaf(h1.x, WB.y, accB.z); accB.w = fmaf(h1.y, WB.y, accB.w);
                const float2 l2 = __half22float2(*reinterpret_cast<const __half2*>(&gB2.x));
                const float2 h2 = __half22float2(*reinterpret_cast<const __half2*>(&gB2.y));
                accB.x = fmaf(l2.x, WB.z, accB.x); accB.y = fmaf(l2.y, WB.z, accB.y);
                accB.z = fmaf(h2.x, WB.z, accB.z); accB.w = fmaf(h2.y, WB.z, accB.w);
                const float2 l3 = __half22float2(*reinterpret_cast<const __half2*>(&gB3.x));
                const float2 h3 = __half22float2(*reinterpret_cast<const __half2*>(&gB3.y));
                accB.x = fmaf(l3.x, WB.w, accB.x); accB.y = fmaf(l3.y, WB.w, accB.y);
                accB.z = fmaf(h3.x, WB.w, accB.z); accB.w = fmaf(h3.y, WB.w, accB.w);
            }
        }

        // Reduce each chain across the 8 quads.
#pragma unroll
        for (int mask = 4; mask <= 16; mask <<= 1) {
            accA.x += __shfl_xor_sync(0xffffffffu, accA.x, mask);
            accA.y += __shfl_xor_sync(0xffffffffu, accA.y, mask);
            accA.z += __shfl_xor_sync(0xffffffffu, accA.z, mask);
            accA.w += __shfl_xor_sync(0xffffffffu, accA.w, mask);
            accB.x += __shfl_xor_sync(0xffffffffu, accB.x, mask);
            accB.y += __shfl_xor_sync(0xffffffffu, accB.y, mask);
            accB.z += __shfl_xor_sync(0xffffffffu, accB.z, mask);
            accB.w += __shfl_xor_sync(0xffffffffu, accB.w, mask);
        }

        if (q == 0) {
            {
                const float bias = gb[pA];
                float* r = s_res + (ph * TPB + pA) * SB + c * 4;
                float vx = accA.x + bias, vy = accA.y + bias;
                float vz = accA.z + bias, vw = accA.w + bias;
                r[0] = (vx > 0.f) ? vx : 0.3f * vx;
                r[1] = (vy > 0.f) ? vy : 0.3f * vy;
                r[2] = (vz > 0.f) ? vz : 0.3f * vz;
                r[3] = (vw > 0.f) ? vw : 0.3f * vw;
            }
            if (hasB) {
                const float bias = gb[pB];
                float* r = s_res + (ph * TPB + pB) * SB + c * 4;
                float vx = accB.x + bias, vy = accB.y + bias;
                float vz = accB.z + bias, vw = accB.w + bias;
                r[0] = (vx > 0.f) ? vx : 0.3f * vx;
                r[1] = (vy > 0.f) ? vy : 0.3f * vy;
                r[2] = (vz > 0.f) ? vz : 0.3f * vz;
                r[3] = (vw > 0.f) ? vw : 0.3f * vw;
            }
        }
    }
    __syncthreads();

    // ---- Coalesced store: warp = batch, 32 lanes = 32 consecutive p ----
    if (lane < width) {
#pragma unroll 1
        for (int ph = 0; ph < NPH; ph++) {
            const int   st = row + ph * st_step;
            const float y  = s_res[(ph * TPB + lane) * SB + w];
            if (is_main) {
                long o = (long)w * TLEN * P_OUT
                       + (long)(st * STRETCH) * P_OUT + p0 + lane;
#pragma unroll
                for (int r = 0; r < STRETCH; r++) {
                    out[o + (long)r * P_OUT] = y;   // 128B rows per STG
                }
            } else {
                out[(long)w * TLEN * P_OUT + (long)st * P_OUT
                    + NB_PATCH + p0 + lane] = y;
            }
        }
    }
}

// --------------------------------------------------------------------------
// Inputs (metadata order): x, W_main, b_main, W_top, b_top, idx_main, idx_top
// --------------------------------------------------------------------------
extern "C" void kernel_launch(void* const* d_in, const int* in_sizes, int n_in,
                              void* d_out, int out_size) {
    const float* x        = (const float*)d_in[0];
    const float* W_main   = (const float*)d_in[1];
    const float* b_main   = (const float*)d_in[2];
    const float* W_top    = (const float*)d_in[3];
    const float* b_top    = (const float*)d_in[4];
    const int*   idx_main = (const int*)  d_in[5];
    const int*   idx_top  = (const int*)  d_in[6];
    float* out = (float*)d_out;

    transpose_x_kernel<<<(TC + 255) / 256, 256>>>(x);

    patchy_kernel<<<ALL_BLK2, THREADS>>>(W_main, b_main, W_top, b_top,
                                         idx_main, idx_top, out);
}

// round 16
// speedup vs baseline: 1.1332x; 1.1332x over previous
#include <cuda_runtime.h>
#include <cuda_fp16.h>
#include <cuda_bf16.h>
#include <cstdint>

// Problem constants (fixed shapes from reference)
#define BATCH      16
#define TLEN       1024
#define CCH        32
#define TC         (TLEN * CCH)        // 32768
#define KDIM       128
#define S_MAIN     128
#define NB_PATCH   400
#define P_TOP      60
#define P_OUT      (NB_PATCH + P_TOP)  // 460
#define STRETCH    8

#define THREADS    256                 // 8 warps; each warp owns up to 2 tasks
#define TPB        16                  // tasks (p columns) per block
#define SB         17                  // s_res row stride (conflict-free-ish)
#define MAIN_PB    (NB_PATCH / TPB)    // 25 (exact: width always 16)
#define TOP_PB     ((P_TOP + TPB - 1) / TPB)     // 4 (widths 16,16,16,12)
#define MAIN_BLOCKS (S_MAIN * MAIN_PB) // 3200
#define TOP_BLOCKS  (TLEN * TOP_PB)    // 4096
#define ALL_BLOCKS  (MAIN_BLOCKS + TOP_BLOCKS)   // 7296

// Scratch: transposed fp16 x, xTh[tc][b]. One gather index pulls 16 halves
// = 32B (one L2 sector) holding all 16 batch values.
__device__ __align__(32) __half g_xTh[TC * BATCH];

// --------------------------------------------------------------------------
// Kernel 1: transpose + fp16-quantize x [B, T*C] -> xTh [T*C, B]
// --------------------------------------------------------------------------
__global__ void transpose_x_kernel(const float* __restrict__ x) {
    int tc = blockIdx.x * blockDim.x + threadIdx.x;
    if (tc >= TC) return;
    __half2 h[8];
#pragma unroll
    for (int b = 0; b < 8; b++) {
        h[b] = __floats2half2_rn(x[(2 * b) * TC + tc], x[(2 * b + 1) * TC + tc]);
    }
    uint4* dst = reinterpret_cast<uint4*>(g_xTh + tc * BATCH);
    unsigned int* hu = reinterpret_cast<unsigned int*>(h);
    dst[0] = make_uint4(hu[0], hu[1], hu[2], hu[3]);
    dst[1] = make_uint4(hu[4], hu[5], hu[6], hu[7]);
}

// --------------------------------------------------------------------------
// Kernel 2: fused main + top patch layers.  (R13 hot loop, small blocks)
// Block = 8 warps covering 16 consecutive p of one (s|t) row; 4 CTAs/SM ->
// double the independent barrier domains / CTA turnover vs 16-warp blocks,
// so one block's reduce/store tail overlaps three other CTAs' gathers.
// Warp w owns tasks pA = w and pB = w+8: two INDEPENDENT gather->FMA
// chains per warp. Absent B task aliases pA (warp-uniform pointer SEL;
// duplicate gathers become L1 hits). Main widths are exactly 16 -> no
// aliased waste on main at all.
// Lane = (q = lane>>2, c = lane&3):
//   - idx/W per chain: int4/float4 at [m*8+q] (128B per warp-load, 1 wf),
//   - gathers: quad q fetches row idx, lane reads 8B (batches 4c..4c+3),
//   - reduce via shfl_xor(4,8,16); q==0 lanes hold all 16 batches,
//   - padded smem stage; store: lanes 0-15 = p for batch w, lanes 16-31 =
//     p for batch w+8 (two 64B segments per STG), main repeated x8.
// --------------------------------------------------------------------------
__global__ __launch_bounds__(THREADS, 4) void patchy_kernel(
    const float* __restrict__ W_main, const float* __restrict__ b_main,
    const float* __restrict__ W_top,  const float* __restrict__ b_top,
    const int*   __restrict__ idx_main, const int* __restrict__ idx_top,
    float* __restrict__ out)
{
    __shared__ float s_res[TPB * SB];

    const int tid  = threadIdx.x;
    const int w    = tid >> 5;       // warp id: local pA (compute)
    const int lane = tid & 31;
    const int q    = lane >> 2;      // quad: sub-index group
    const int c    = lane & 3;       // component: batches 4c..4c+3
    const bool is_main = (blockIdx.x < MAIN_BLOCKS);

    int st, p0, width;
    const int*   gi;
    const float* gw;
    const float* gb;
    if (is_main) {
        st    = blockIdx.x / MAIN_PB;
        p0    = (blockIdx.x - st * MAIN_PB) * TPB;
        width = TPB;                                  // 400 = 25*16 exact
        const long base = ((long)st * NB_PATCH + p0) * KDIM;
        gi = idx_main + base;
        gw = W_main   + base;
        gb = b_main   + st * NB_PATCH + p0;
    } else {
        const int b2 = blockIdx.x - MAIN_BLOCKS;
        st    = b2 >> 2;
        p0    = (b2 & 3) * TPB;
        width = min(TPB, P_TOP - p0);
        const long base = ((long)st * P_TOP + p0) * KDIM;
        gi = idx_top + base;
        gw = W_top   + base;
        gb = b_top   + st * P_TOP + p0;
    }

    // Two tasks per warp; absent task aliases pA (gathers become L1 hits).
    const int  pA   = w;
    const int  pB   = w + 8;
    const bool hasB = (pB < width);
    const int  pBc  = hasB ? pB : pA;

    {
        const int4*   ipA = reinterpret_cast<const int4*>(gi + pA  * KDIM);
        const int4*   ipB = reinterpret_cast<const int4*>(gi + pBc * KDIM);
        const float4* wpA = reinterpret_cast<const float4*>(gw + pA  * KDIM);
        const float4* wpB = reinterpret_cast<const float4*>(gw + pBc * KDIM);
        const uint2* __restrict__ xT2 = reinterpret_cast<const uint2*>(g_xTh);

        float4 accA = make_float4(0.f, 0.f, 0.f, 0.f);
        float4 accB = make_float4(0.f, 0.f, 0.f, 0.f);

#pragma unroll
        for (int m = 0; m < 4; m++) {
            // Interleaved independent chains: A's and B's gathers are both
            // in flight while either chain's FMAs execute.
            const int4 IA = ipA[m * 8 + q];
            const int4 IB = ipB[m * 8 + q];

            const uint2 gA0 = xT2[IA.x * 4 + c];
            const uint2 gA1 = xT2[IA.y * 4 + c];
            const uint2 gA2 = xT2[IA.z * 4 + c];
            const uint2 gA3 = xT2[IA.w * 4 + c];
            const uint2 gB0 = xT2[IB.x * 4 + c];
            const uint2 gB1 = xT2[IB.y * 4 + c];
            const uint2 gB2 = xT2[IB.z * 4 + c];
            const uint2 gB3 = xT2[IB.w * 4 + c];

            const float4 WA = wpA[m * 8 + q];
            const float4 WB = wpB[m * 8 + q];

            {
                const float2 l0 = __half22float2(*reinterpret_cast<const __half2*>(&gA0.x));
                const float2 h0 = __half22float2(*reinterpret_cast<const __half2*>(&gA0.y));
                accA.x = fmaf(l0.x, WA.x, accA.x); accA.y = fmaf(l0.y, WA.x, accA.y);
                accA.z = fmaf(h0.x, WA.x, accA.z); accA.w = fmaf(h0.y, WA.x, accA.w);
                const float2 l1 = __half22float2(*reinterpret_cast<const __half2*>(&gA1.x));
                const float2 h1 = __half22float2(*reinterpret_cast<const __half2*>(&gA1.y));
                accA.x = fmaf(l1.x, WA.y, accA.x); accA.y = fmaf(l1.y, WA.y, accA.y);
                accA.z = fmaf(h1.x, WA.y, accA.z); accA.w = fmaf(h1.y, WA.y, accA.w);
                const float2 l2 = __half22float2(*reinterpret_cast<const __half2*>(&gA2.x));
                const float2 h2 = __half22float2(*reinterpret_cast<const __half2*>(&gA2.y));
                accA.x = fmaf(l2.x, WA.z, accA.x); accA.y = fmaf(l2.y, WA.z, accA.y);
                accA.z = fmaf(h2.x, WA.z, accA.z); accA.w = fmaf(h2.y, WA.z, accA.w);
                const float2 l3 = __half22float2(*reinterpret_cast<const __half2*>(&gA3.x));
                const float2 h3 = __half22float2(*reinterpret_cast<const __half2*>(&gA3.y));
                accA.x = fmaf(l3.x, WA.w, accA.x); accA.y = fmaf(l3.y, WA.w, accA.y);
                accA.z = fmaf(h3.x, WA.w, accA.z); accA.w = fmaf(h3.y, WA.w, accA.w);
            }
            {
                const float2 l0 = __half22float2(*reinterpret_cast<const __half2*>(&gB0.x));
                const float2 h0 = __half22float2(*reinterpret_cast<const __half2*>(&gB0.y));
                accB.x = fmaf(l0.x, WB.x, accB.x); accB.y = fmaf(l0.y, WB.x, accB.y);
                accB.z = fmaf(h0.x, WB.x, accB.z); accB.w = fmaf(h0.y, WB.x, accB.w);
                const float2 l1 = __half22float2(*reinterpret_cast<const __half2*>(&gB1.x));
                const float2 h1 = __half22float2(*reinterpret_cast<const __half2*>(&gB1.y));
                accB.x = fmaf(l1.x, WB.y, accB.x); accB.y = fmaf(l1.y, WB.y, accB.y);
                accB.z = fmaf(h1.x, WB.y, accB.z); accB.w = fmaf(h1.y, WB.y, accB.w);
                const float2 l2 = __half22float2(*reinterpret_cast<const __half2*>(&gB2.x));
                const float2 h2 = __half22float2(*reinterpret_cast<const __half2*>(&gB2.y));
                accB.x = fmaf(l2.x, WB.z, accB.x); accB.y = fmaf(l2.y, WB.z, accB.y);
                accB.z = fmaf(h2.x, WB.z, accB.z); accB.w = fmaf(h2.y, WB.z, accB.w);
                const float2 l3 = __half22float2(*reinterpret_cast<const __half2*>(&gB3.x));
                const float2 h3 = __half22float2(*reinterpret_cast<const __half2*>(&gB3.y));
                accB.x = fmaf(l3.x, WB.w, accB.x); accB.y = fmaf(l3.y, WB.w, accB.y);
                accB.z = fmaf(h3.x, WB.w, accB.z); accB.w = fmaf(h3.y, WB.w, accB.w);
            }
        }

        // Reduce each chain across the 8 quads.
#pragma unroll
        for (int mask = 4; mask <= 16; mask <<= 1) {
            accA.x += __shfl_xor_sync(0xffffffffu, accA.x, mask);
            accA.y += __shfl_xor_sync(0xffffffffu, accA.y, mask);
            accA.z += __shfl_xor_sync(0xffffffffu, accA.z, mask);
            accA.w += __shfl_xor_sync(0xffffffffu, accA.w, mask);
            accB.x += __shfl_xor_sync(0xffffffffu, accB.x, mask);
            accB.y += __shfl_xor_sync(0xffffffffu, accB.y, mask);
            accB.z += __shfl_xor_sync(0xffffffffu, accB.z, mask);
            accB.w += __shfl_xor_sync(0xffffffffu, accB.w, mask);
        }

        if (q == 0) {
            {
                const float bias = gb[pA];
                float* r = s_res + pA * SB + c * 4;
                float vx = accA.x + bias, vy = accA.y + bias;
                float vz = accA.z + bias, vw = accA.w + bias;
                r[0] = (vx > 0.f) ? vx : 0.3f * vx;
                r[1] = (vy > 0.f) ? vy : 0.3f * vy;
                r[2] = (vz > 0.f) ? vz : 0.3f * vz;
                r[3] = (vw > 0.f) ? vw : 0.3f * vw;
            }
            if (hasB) {
                const float bias = gb[pB];
                float* r = s_res + pB * SB + c * 4;
                float vx = accB.x + bias, vy = accB.y + bias;
                float vz = accB.z + bias, vw = accB.w + bias;
                r[0] = (vx > 0.f) ? vx : 0.3f * vx;
                r[1] = (vy > 0.f) ? vy : 0.3f * vy;
                r[2] = (vz > 0.f) ? vz : 0.3f * vz;
                r[3] = (vw > 0.f) ? vw : 0.3f * vw;
            }
        }
    }
    __syncthreads();

    // ---- Coalesced store: lanes 0-15 = p for batch w, lanes 16-31 = p for
    //      batch w+8; each STG writes two 64B segments ----
    {
        const int j = lane & 15;             // local p
        const int b = w + ((lane >> 4) << 3); // batch: w or w+8
        if (j < width) {
            const float y = s_res[j * SB + b];
            if (is_main) {
                long o = (long)b * TLEN * P_OUT
                       + (long)(st * STRETCH) * P_OUT + p0 + j;
#pragma unroll
                for (int r = 0; r < STRETCH; r++) {
                    out[o + (long)r * P_OUT] = y;
                }
            } else {
                out[(long)b * TLEN * P_OUT + (long)st * P_OUT
                    + NB_PATCH + p0 + j] = y;
            }
        }
    }
}

// --------------------------------------------------------------------------
// Inputs (metadata order): x, W_main, b_main, W_top, b_top, idx_main, idx_top
// --------------------------------------------------------------------------
extern "C" void kernel_launch(void* const* d_in, const int* in_sizes, int n_in,
                              void* d_out, int out_size) {
    const float* x        = (const float*)d_in[0];
    const float* W_main   = (const float*)d_in[1];
    const float* b_main   = (const float*)d_in[2];
    const float* W_top    = (const float*)d_in[3];
    const float* b_top    = (const float*)d_in[4];
    const int*   idx_main = (const int*)  d_in[5];
    const int*   idx_top  = (const int*)  d_in[6];
    float* out = (float*)d_out;

    transpose_x_kernel<<<(TC + 255) / 256, 256>>>(x);

    patchy_kernel<<<ALL_BLOCKS, THREADS>>>(W_main, b_main, W_top, b_top,
                                           idx_main, idx_top, out);
}

// round 17
// speedup vs baseline: 1.1410x; 1.0069x over previous
#include <cuda_runtime.h>
#include <cuda_fp16.h>
#include <cuda_bf16.h>
#include <cstdint>

// Problem constants (fixed shapes from reference)
#define BATCH      16
#define TLEN       1024
#define CCH        32
#define TC         (TLEN * CCH)        // 32768
#define KDIM       128
#define S_MAIN     128
#define NB_PATCH   400
#define P_TOP      60
#define P_OUT      (NB_PATCH + P_TOP)  // 460
#define STRETCH    8

#define THREADS    256                 // 8 warps; each warp owns 2 chains
#define CPB        16                  // chains (tasks) per block
#define SB         17                  // s_res row stride (conflict-free)
#define MAIN_TASKS (S_MAIN * NB_PATCH) // 51200 = 3200*16 exact
#define TOP_TASKS  (TLEN * P_TOP)      // 61440 = 3840*16 exact
#define MAIN_BLOCKS (MAIN_TASKS / CPB) // 3200
#define TOP_BLOCKS  (TOP_TASKS / CPB)  // 3840
#define ALL_BLOCKS  (MAIN_BLOCKS + TOP_BLOCKS)   // 7040

// Scratch: transposed fp16 x, xTh[tc][b]. One gather index pulls 16 halves
// = 32B (one L2 sector) holding all 16 batch values.
__device__ __align__(32) __half g_xTh[TC * BATCH];

// --------------------------------------------------------------------------
// Kernel 1: transpose + fp16-quantize x [B, T*C] -> xTh [T*C, B]
// --------------------------------------------------------------------------
__global__ void transpose_x_kernel(const float* __restrict__ x) {
    int tc = blockIdx.x * blockDim.x + threadIdx.x;
    if (tc >= TC) return;
    __half2 h[8];
#pragma unroll
    for (int b = 0; b < 8; b++) {
        h[b] = __floats2half2_rn(x[(2 * b) * TC + tc], x[(2 * b + 1) * TC + tc]);
    }
    uint4* dst = reinterpret_cast<uint4*>(g_xTh + tc * BATCH);
    unsigned int* hu = reinterpret_cast<unsigned int*>(h);
    dst[0] = make_uint4(hu[0], hu[1], hu[2], hu[3]);
    dst[1] = make_uint4(hu[4], hu[5], hu[6], hu[7]);
}

// --------------------------------------------------------------------------
// Kernel 2: fused main + top patch layers.  (flat chain assignment)
// Both idx/W tables are [rows, P, K] -> a flat task id addresses them as
// base + task*K. Each block owns 16 CONSECUTIVE flat tasks (both regions
// divide exactly), so every warp's two chains are real work - zero aliased
// waste, no hasB clamp, unconditional hot loop (same schedule as R15).
// Warp w owns chains cA = w and cB = w+8: two INDEPENDENT gather->FMA
// chains per warp. 4 CTAs/SM for tail overlap.
// Lane = (q = lane>>2, c = lane&3):
//   - idx/W per chain: int4/float4 at [m*8+q] (128B per warp-load, 1 wf),
//   - gathers: quad q fetches row idx, lane reads 8B (batches 4c..4c+3),
//   - reduce via shfl_xor(4,8,16); q==0 lanes hold all 16 batches,
//   - padded smem stage; store: j = lane&15 (local task), b = w | ((lane>>4)<<3);
//     main: block-uniform row, p = p0+j (64B segments, x8 time reps);
//     top: per-lane (t,p) = (tau/60, tau%60) via magic-multiply.
// --------------------------------------------------------------------------
__global__ __launch_bounds__(THREADS, 4) void patchy_kernel(
    const float* __restrict__ W_main, const float* __restrict__ b_main,
    const float* __restrict__ W_top,  const float* __restrict__ b_top,
    const int*   __restrict__ idx_main, const int* __restrict__ idx_top,
    float* __restrict__ out)
{
    __shared__ float s_res[CPB * SB];

    const int tid  = threadIdx.x;
    const int w    = tid >> 5;       // warp id
    const int lane = tid & 31;
    const int q    = lane >> 2;      // quad: sub-index group
    const int c    = lane & 3;       // component: batches 4c..4c+3
    const bool is_main = (blockIdx.x < MAIN_BLOCKS);

    // Flat base task of this block within its region, and per-warp chains.
    int tbase;
    const int*   gi;
    const float* gw;
    const float* gb;
    if (is_main) {
        tbase = blockIdx.x * CPB;
        gi = idx_main; gw = W_main; gb = b_main;
    } else {
        tbase = (blockIdx.x - MAIN_BLOCKS) * CPB;
        gi = idx_top;  gw = W_top;  gb = b_top;
    }
    const int tA = tbase + w;        // chain A task
    const int tB = tbase + w + 8;    // chain B task

    {
        const int4*   ipA = reinterpret_cast<const int4*>(gi + (long)tA * KDIM);
        const int4*   ipB = reinterpret_cast<const int4*>(gi + (long)tB * KDIM);
        const float4* wpA = reinterpret_cast<const float4*>(gw + (long)tA * KDIM);
        const float4* wpB = reinterpret_cast<const float4*>(gw + (long)tB * KDIM);
        const uint2* __restrict__ xT2 = reinterpret_cast<const uint2*>(g_xTh);

        float4 accA = make_float4(0.f, 0.f, 0.f, 0.f);
        float4 accB = make_float4(0.f, 0.f, 0.f, 0.f);

#pragma unroll
        for (int m = 0; m < 4; m++) {
            // Interleaved independent chains: A's and B's gathers are both
            // in flight while either chain's FMAs execute.
            const int4 IA = ipA[m * 8 + q];
            const int4 IB = ipB[m * 8 + q];

            const uint2 gA0 = xT2[IA.x * 4 + c];
            const uint2 gA1 = xT2[IA.y * 4 + c];
            const uint2 gA2 = xT2[IA.z * 4 + c];
            const uint2 gA3 = xT2[IA.w * 4 + c];
            const uint2 gB0 = xT2[IB.x * 4 + c];
            const uint2 gB1 = xT2[IB.y * 4 + c];
            const uint2 gB2 = xT2[IB.z * 4 + c];
            const uint2 gB3 = xT2[IB.w * 4 + c];

            const float4 WA = wpA[m * 8 + q];
            const float4 WB = wpB[m * 8 + q];

            {
                const float2 l0 = __half22float2(*reinterpret_cast<const __half2*>(&gA0.x));
                const float2 h0 = __half22float2(*reinterpret_cast<const __half2*>(&gA0.y));
                accA.x = fmaf(l0.x, WA.x, accA.x); accA.y = fmaf(l0.y, WA.x, accA.y);
                accA.z = fmaf(h0.x, WA.x, accA.z); accA.w = fmaf(h0.y, WA.x, accA.w);
                const float2 l1 = __half22float2(*reinterpret_cast<const __half2*>(&gA1.x));
                const float2 h1 = __half22float2(*reinterpret_cast<const __half2*>(&gA1.y));
                accA.x = fmaf(l1.x, WA.y, accA.x); accA.y = fmaf(l1.y, WA.y, accA.y);
                accA.z = fmaf(h1.x, WA.y, accA.z); accA.w = fmaf(h1.y, WA.y, accA.w);
                const float2 l2 = __half22float2(*reinterpret_cast<const __half2*>(&gA2.x));
                const float2 h2 = __half22float2(*reinterpret_cast<const __half2*>(&gA2.y));
                accA.x = fmaf(l2.x, WA.z, accA.x); accA.y = fmaf(l2.y, WA.z, accA.y);
                accA.z = fmaf(h2.x, WA.z, accA.z); accA.w = fmaf(h2.y, WA.z, accA.w);
                const float2 l3 = __half22float2(*reinterpret_cast<const __half2*>(&gA3.x));
                const float2 h3 = __half22float2(*reinterpret_cast<const __half2*>(&gA3.y));
                accA.x = fmaf(l3.x, WA.w, accA.x); accA.y = fmaf(l3.y, WA.w, accA.y);
                accA.z = fmaf(h3.x, WA.w, accA.z); accA.w = fmaf(h3.y, WA.w, accA.w);
            }
            {
                const float2 l0 = __half22float2(*reinterpret_cast<const __half2*>(&gB0.x));
                const float2 h0 = __half22float2(*reinterpret_cast<const __half2*>(&gB0.y));
                accB.x = fmaf(l0.x, WB.x, accB.x); accB.y = fmaf(l0.y, WB.x, accB.y);
                accB.z = fmaf(h0.x, WB.x, accB.z); accB.w = fmaf(h0.y, WB.x, accB.w);
                const float2 l1 = __half22float2(*reinterpret_cast<const __half2*>(&gB1.x));
                const float2 h1 = __half22float2(*reinterpret_cast<const __half2*>(&gB1.y));
                accB.x = fmaf(l1.x, WB.y, accB.x); accB.y = fmaf(l1.y, WB.y, accB.y);
                accB.z = fmaf(h1.x, WB.y, accB.z); accB.w = fmaf(h1.y, WB.y, accB.w);
                const float2 l2 = __half22float2(*reinterpret_cast<const __half2*>(&gB2.x));
                const float2 h2 = __half22float2(*reinterpret_cast<const __half2*>(&gB2.y));
                accB.x = fmaf(l2.x, WB.z, accB.x); accB.y = fmaf(l2.y, WB.z, accB.y);
                accB.z = fmaf(h2.x, WB.z, accB.z); accB.w = fmaf(h2.y, WB.z, accB.w);
                const float2 l3 = __half22float2(*reinterpret_cast<const __half2*>(&gB3.x));
                const float2 h3 = __half22float2(*reinterpret_cast<const __half2*>(&gB3.y));
                accB.x = fmaf(l3.x, WB.w, accB.x); accB.y = fmaf(l3.y, WB.w, accB.y);
                accB.z = fmaf(h3.x, WB.w, accB.z); accB.w = fmaf(h3.y, WB.w, accB.w);
            }
        }

        // Reduce each chain across the 8 quads.
#pragma unroll
        for (int mask = 4; mask <= 16; mask <<= 1) {
            accA.x += __shfl_xor_sync(0xffffffffu, accA.x, mask);
            accA.y += __shfl_xor_sync(0xffffffffu, accA.y, mask);
            accA.z += __shfl_xor_sync(0xffffffffu, accA.z, mask);
            accA.w += __shfl_xor_sync(0xffffffffu, accA.w, mask);
            accB.x += __shfl_xor_sync(0xffffffffu, accB.x, mask);
            accB.y += __shfl_xor_sync(0xffffffffu, accB.y, mask);
            accB.z += __shfl_xor_sync(0xffffffffu, accB.z, mask);
            accB.w += __shfl_xor_sync(0xffffffffu, accB.w, mask);
        }

        if (q == 0) {
            {
                const float bias = gb[tA];
                float* r = s_res + w * SB + c * 4;
                float vx = accA.x + bias, vy = accA.y + bias;
                float vz = accA.z + bias, vw = accA.w + bias;
                r[0] = (vx > 0.f) ? vx : 0.3f * vx;
                r[1] = (vy > 0.f) ? vy : 0.3f * vy;
                r[2] = (vz > 0.f) ? vz : 0.3f * vz;
                r[3] = (vw > 0.f) ? vw : 0.3f * vw;
            }
            {
                const float bias = gb[tB];
                float* r = s_res + (w + 8) * SB + c * 4;
                float vx = accB.x + bias, vy = accB.y + bias;
                float vz = accB.z + bias, vw = accB.w + bias;
                r[0] = (vx > 0.f) ? vx : 0.3f * vx;
                r[1] = (vy > 0.f) ? vy : 0.3f * vy;
                r[2] = (vz > 0.f) ? vz : 0.3f * vz;
                r[3] = (vw > 0.f) ? vw : 0.3f * vw;
            }
        }
    }
    __syncthreads();

    // ---- Coalesced store: j = local task (lane&15), b = w or w+8 ----
    {
        const int j = lane & 15;              // local task index
        const int b = w + ((lane >> 4) << 3); // batch
        const float y = s_res[j * SB + b];
        if (is_main) {
            // main never straddles a row: s uniform, p = p0 + j
            const int mu = tbase;             // = s*400 + p0
            const int s  = mu / NB_PATCH;
            const int p  = mu - s * NB_PATCH + j;
            long o = (long)b * TLEN * P_OUT
                   + (long)(s * STRETCH) * P_OUT + p;
#pragma unroll
            for (int r = 0; r < STRETCH; r++) {
                out[o + (long)r * P_OUT] = y;
            }
        } else {
            const int tau = tbase + j;        // flat top task
            const int t   = tau / P_TOP;      // magic-multiply
            const int p   = tau - t * P_TOP;
            out[(long)b * TLEN * P_OUT + (long)t * P_OUT + NB_PATCH + p] = y;
        }
    }
}

// --------------------------------------------------------------------------
// Inputs (metadata order): x, W_main, b_main, W_top, b_top, idx_main, idx_top
// --------------------------------------------------------------------------
extern "C" void kernel_launch(void* const* d_in, const int* in_sizes, int n_in,
                              void* d_out, int out_size) {
    const float* x        = (const float*)d_in[0];
    const float* W_main   = (const float*)d_in[1];
    const float* b_main   = (const float*)d_in[2];
    const float* W_top    = (const float*)d_in[3];
    const float* b_top    = (const float*)d_in[4];
    const int*   idx_main = (const int*)  d_in[5];
    const int*   idx_top  = (const int*)  d_in[6];
    float* out = (float*)d_out;

    transpose_x_kernel<<<(TC + 255) / 256, 256>>>(x);

    patchy_kernel<<<ALL_BLOCKS, THREADS>>>(W_main, b_main, W_top, b_top,
                                           idx_main, idx_top, out);
}